// round 15
// baseline (speedup 1.0000x reference)
#include <cuda_runtime.h>
#include <cuda_fp16.h>
#include <cstdint>
#include <cstddef>

// ---------------------------------------------------------------------------
// Problem constants
// ---------------------------------------------------------------------------
#define Bsz 8
#define Lsz 1024
#define Hsz 1024
#define Msz 128
#define Vsz 32
#define VV  (Vsz * Vsz)          // 1024
#define LN_EPS 1e-5f
#define NCHUNK 32                // storage granularity: K chunks of 32
#define LG_NCH 16                // logits: K chunks of 64 per tile
#define NTILE  4096              // logits work items (4 ntile-pairs x 1024 bi)
#define NPERS  148               // persistent CTAs

// Output layout offsets (floats)
static const size_t OFF_LOGITS = 0;
static const size_t OFF_MLM    = 134217728;
static const size_t OFF_DIAG   = OFF_MLM + (size_t)Bsz * Lsz * Vsz;
static const size_t OFF_MASKAA = OFF_DIAG + (size_t)Bsz * Msz * Msz;
static const size_t OFF_PAIR   = OFF_MASKAA + (size_t)Bsz * Lsz;

// ---------------------------------------------------------------------------
// Device scratch
// ---------------------------------------------------------------------------
__device__ float  g_xm[(size_t)Bsz * Msz * Hsz];     // 4 MB (gathered LN rows)
__device__ float  g_q [(size_t)Bsz * Msz * Hsz];     // 4 MB
__device__ __half g_kh[(size_t)Bsz * Msz * Hsz];     // 2 MB (k in fp16)
__device__ int    g_inv[Bsz * Lsz];                  // l -> m (or -1)
__device__ float  g_Wmt[Hsz * Vsz];                  // W_mlm transposed [h][v]

// W_embed fp16 (single-rounded), mma B-frag paired-nf layout per (nt, chunk32)
__device__ __align__(1024) uint8_t g_Wt[8 * NCHUNK * 8192];            // 2 MB
// Wq/Wk split hi/lo fp16: [mat(2)][ot(8)][chunk(32)] x 16KB = [hi|lo]
__device__ __align__(1024) uint8_t g_Wqk[2 * 8 * NCHUNK * 16384];      // 8 MB
// xm fp16 A-frag: [mtile(8)][chunk(32)] x 8KB
__device__ __align__(1024) uint8_t g_Xt[8 * NCHUNK * 8192];            // 2 MB
// A' = q (.) k fp16 A-frag per (bi, chunk32)
__device__ __align__(1024) uint8_t g_At[(size_t)1024 * NCHUNK * 8192]; // 256 MB

// ---------------------------------------------------------------------------
// Helpers
// ---------------------------------------------------------------------------
__device__ __forceinline__ uint32_t smem_u32(const void* p) {
    uint32_t a;
    asm("{ .reg .u64 t; cvta.to.shared.u64 t, %1; cvt.u32.u64 %0, t; }"
        : "=r"(a) : "l"(p));
    return a;
}

__device__ __forceinline__ uint32_t pack_f16(float lo, float hi) {
    uint32_t r;
    asm("cvt.rn.f16x2.f32 %0, %1, %2;" : "=r"(r) : "f"(hi), "f"(lo));
    return r;
}
__device__ __forceinline__ void split2_f16(float x0, float x1, uint32_t& h, uint32_t& l) {
    h = pack_f16(x0, x1);
    float h0, h1;
    asm("{.reg .f16 a,b; mov.b32 {a,b}, %2; cvt.f32.f16 %0, a; cvt.f32.f16 %1, b;}"
        : "=f"(h0), "=f"(h1) : "r"(h));
    l = pack_f16(x0 - h0, x1 - h1);
}

#define CP_ASYNC16(dst_u32, src_ptr) \
    asm volatile("cp.async.cg.shared.global [%0], [%1], 16;" \
                 :: "r"(dst_u32), "l"(src_ptr) : "memory")
#define CP_COMMIT()  asm volatile("cp.async.commit_group;" ::: "memory")
#define CP_WAIT0()   asm volatile("cp.async.wait_group 0;" ::: "memory")
#define CP_WAIT1()   asm volatile("cp.async.wait_group 1;" ::: "memory")
#define CP_WAIT2()   asm volatile("cp.async.wait_group 2;" ::: "memory")

#define MMA_F16(c, a, bb) \
    asm volatile("mma.sync.aligned.m16n8k16.row.col.f32.f16.f16.f32 " \
                 "{%0,%1,%2,%3},{%4,%5,%6,%7},{%8,%9},{%0,%1,%2,%3};" \
                 : "+f"((c)[0]), "+f"((c)[1]), "+f"((c)[2]), "+f"((c)[3]) \
                 : "r"((a)[0]), "r"((a)[1]), "r"((a)[2]), "r"((a)[3]), \
                   "r"((bb)[0]), "r"((bb)[1]))

// ---------------------------------------------------------------------------
// Kernel P: merged preprocessing.
// blocks [0,256): W_embed split ; [256,768): Wq/Wk split ;
// [768,896): W_mlm transpose ; [896,904): inverse mask index.
// ---------------------------------------------------------------------------
__global__ __launch_bounds__(256) void prep_kernel(
    const float* __restrict__ W, const float* __restrict__ Wq,
    const float* __restrict__ Wk, const float* __restrict__ Wm,
    const int* __restrict__ mask_idx)
{
    const int bz = blockIdx.x, tid = threadIdx.x;

    if (bz < 256) {
        const int ch = bz & 31, nt = bz >> 5;
        const int v  = tid >> 1;
        const int sh = tid & 1;
        const float4* src = (const float4*)(W + (size_t)(nt * 128 + v) * Hsz + ch * 32 + sh * 16);
        uint8_t* tile = g_Wt + (size_t)(nt * NCHUNK + ch) * 8192;
        const int nfp  = v >> 4;
        const int half = (v >> 3) & 1;
        const int lbase = (v & 7) * 4;
        #pragma unroll
        for (int g = 0; g < 4; g++) {
            float4 x = src[g];
            #pragma unroll
            for (int e = 0; e < 2; e++) {
                const int pl = g * 2 + e;
                uint32_t h = (e == 0) ? pack_f16(x.x, x.y) : pack_f16(x.z, x.w);
                const uint32_t off =
                    (uint32_t)(((sh * 8 + nfp) * 32 + lbase + (pl & 3)) * 16 + half * 8 + (pl >> 2) * 4);
                *(uint32_t*)(tile + off) = h;
            }
        }
    } else if (bz < 768) {
        const int idx = bz - 256;
        const int ch = idx & 31, ot = (idx >> 5) & 7, mat = idx >> 8;
        const float* Wx = mat ? Wk : Wq;
        const int v  = tid >> 1;
        const int sh = tid & 1;
        const float4* src = (const float4*)(Wx + (size_t)(ot * 128 + v) * Hsz + ch * 32 + sh * 16);
        uint8_t* tile = g_Wqk + (size_t)((mat * 8 + ot) * NCHUNK + ch) * 16384;
        const int nfp  = v >> 4;
        const int half = (v >> 3) & 1;
        const int lbase = (v & 7) * 4;
        #pragma unroll
        for (int g = 0; g < 4; g++) {
            float4 x = src[g];
            #pragma unroll
            for (int e = 0; e < 2; e++) {
                const int pl = g * 2 + e;
                uint32_t h, l;
                if (e == 0) split2_f16(x.x, x.y, h, l);
                else        split2_f16(x.z, x.w, h, l);
                const uint32_t off =
                    (uint32_t)(((sh * 8 + nfp) * 32 + lbase + (pl & 3)) * 16 + half * 8 + (pl >> 2) * 4);
                *(uint32_t*)(tile + off)        = h;
                *(uint32_t*)(tile + 8192 + off) = l;
            }
        }
    } else if (bz < 896) {
        const int idx = (bz - 768) * 256 + tid;
        const int h = idx >> 5, v = idx & 31;
        g_Wmt[idx] = Wm[(size_t)v * Hsz + h];
    } else {
        const int b = bz - 896;
        #pragma unroll
        for (int i = tid; i < Lsz; i += 256) g_inv[b * Lsz + i] = -1;
        __syncthreads();
        if (tid < Msz) g_inv[b * Lsz + mask_idx[b * Msz + tid]] = tid;
    }
}

// ---------------------------------------------------------------------------
// Kernel 1: LayerNorm (warp-per-row) + MLM (transposed W) + fused gather.
// ---------------------------------------------------------------------------
__global__ __launch_bounds__(256) void ln_mlm_kernel(
    const float* __restrict__ x, const float* __restrict__ gamma,
    const float* __restrict__ beta, float* __restrict__ out)
{
    __shared__ float sx[8][Hsz];          // 32 KB
    __shared__ float red[8][8][Vsz];      // 8 KB
    const int w = threadIdx.x >> 5, l = threadIdx.x & 31;
    const int row = blockIdx.x * 8 + w;
    const int b   = row >> 10;

    const float4* xr = (const float4*)(x + (size_t)row * Hsz);
    const float4* g4p = (const float4*)gamma;
    const float4* b4p = (const float4*)beta;
    float4 v[8];
    float s = 0.f, ss = 0.f;
    #pragma unroll
    for (int i = 0; i < 8; i++) {
        v[i] = xr[l + i * 32];
        s  += v[i].x + v[i].y + v[i].z + v[i].w;
        ss += v[i].x*v[i].x + v[i].y*v[i].y + v[i].z*v[i].z + v[i].w*v[i].w;
    }
    #pragma unroll
    for (int o = 16; o; o >>= 1) {
        s  += __shfl_xor_sync(0xffffffffu, s,  o);
        ss += __shfl_xor_sync(0xffffffffu, ss, o);
    }
    const float mu = s * (1.0f / Hsz);
    const float rs = rsqrtf(ss * (1.0f / Hsz) - mu * mu + LN_EPS);

    const int inv = g_inv[row];
    float4* xm4 = (float4*)(g_xm + (size_t)(b * Msz + (inv < 0 ? 0 : inv)) * Hsz);
    float4* sx4 = (float4*)sx[w];
    #pragma unroll
    for (int i = 0; i < 8; i++) {
        float4 g = g4p[l + i * 32];
        float4 bb = b4p[l + i * 32];
        float4 n;
        n.x = (v[i].x - mu) * rs * g.x + bb.x;
        n.y = (v[i].y - mu) * rs * g.y + bb.y;
        n.z = (v[i].z - mu) * rs * g.z + bb.z;
        n.w = (v[i].w - mu) * rs * g.w + bb.w;
        sx4[l + i * 32] = n;
        if (inv >= 0) xm4[l + i * 32] = n;
    }
    __syncthreads();

    float p[8];
    #pragma unroll
    for (int r = 0; r < 8; r++) p[r] = 0.f;
    const float* wt = g_Wmt + (size_t)(w * 128) * Vsz + l;
    #pragma unroll 4
    for (int hh = 0; hh < 128; hh++) {
        const int h = w * 128 + hh;
        float wv = wt[hh * Vsz];
        #pragma unroll
        for (int r = 0; r < 8; r++) p[r] += sx[r][h] * wv;
    }
    #pragma unroll
    for (int r = 0; r < 8; r++) red[w][r][l] = p[r];
    __syncthreads();

    float acc = 0.f;
    #pragma unroll
    for (int ww = 0; ww < 8; ww++) acc += red[ww][w][l];
    out[OFF_MLM + (size_t)row * Vsz + l] = acc;
}

// ---------------------------------------------------------------------------
// Kernel 0c: xm -> fp16 A-frag tiles. grid (8 mtiles) x 256.
// ---------------------------------------------------------------------------
__global__ __launch_bounds__(256) void xmsplit_kernel()
{
    const int mt = blockIdx.x;
    const int tid = threadIdx.x;
    const int mt16 = tid >> 5;
    const int lane = tid & 31;
    const int j0 = mt * 128 + mt16 * 16 + (lane >> 2);
    const int j1 = j0 + 8;
    const int kq = (lane & 3) * 2;
    const float* x0 = g_xm + (size_t)j0 * Hsz;
    const float* x1 = g_xm + (size_t)j1 * Hsz;
    uint8_t* outb = g_Xt + (size_t)mt * (NCHUNK * 8192);

    for (int ch = 0; ch < NCHUNK; ch++) {
        #pragma unroll
        for (int s = 0; s < 2; s++) {
            const int kk = ch * 32 + s * 16 + kq;
            float2 a0 = *(const float2*)(x0 + kk);
            float2 a1 = *(const float2*)(x1 + kk);
            float2 b0 = *(const float2*)(x0 + kk + 8);
            float2 b1 = *(const float2*)(x1 + kk + 8);
            uint4 o;
            o.x = pack_f16(a0.x, a0.y);
            o.y = pack_f16(a1.x, a1.y);
            o.z = pack_f16(b0.x, b0.y);
            o.w = pack_f16(b1.x, b1.y);
            *(uint4*)(outb + (size_t)ch * 8192
                       + (size_t)(((s * 8 + mt16) * 32 + lane) * 16)) = o;
        }
    }
}

// ---------------------------------------------------------------------------
// Kernel A: A' = q (.) k fp16 A-frag per bi (k read as fp16). grid 1024 x 256.
// ---------------------------------------------------------------------------
__global__ __launch_bounds__(256) void asplit_kernel()
{
    const int bi = blockIdx.x;
    const int b  = bi >> 7;
    const int tid = threadIdx.x;
    const int mtile = tid >> 5;
    const int lane  = tid & 31;
    const int j0 = mtile * 16 + (lane >> 2);
    const int j1 = j0 + 8;
    const int kq = (lane & 3) * 2;

    const float*  qrow = g_q + (size_t)bi * Hsz;
    const __half* k0r  = g_kh + (size_t)(b * Msz + j0) * Hsz;
    const __half* k1r  = g_kh + (size_t)(b * Msz + j1) * Hsz;
    uint8_t* outb = g_At + (size_t)bi * (NCHUNK * 8192);

    for (int ch = 0; ch < NCHUNK; ch++) {
        #pragma unroll
        for (int s = 0; s < 2; s++) {
            const int kk = ch * 32 + s * 16 + kq;
            float2 qa  = *(const float2*)(qrow + kk);
            float2 qb  = *(const float2*)(qrow + kk + 8);
            float2 k0a = __half22float2(*(const __half2*)(k0r + kk));
            float2 k0b = __half22float2(*(const __half2*)(k0r + kk + 8));
            float2 k1a = __half22float2(*(const __half2*)(k1r + kk));
            float2 k1b = __half22float2(*(const __half2*)(k1r + kk + 8));
            uint4 o;
            o.x = pack_f16(k0a.x * qa.x, k0a.y * qa.y);
            o.y = pack_f16(k1a.x * qa.x, k1a.y * qa.y);
            o.z = pack_f16(k0b.x * qb.x, k0b.y * qb.y);
            o.w = pack_f16(k1b.x * qb.x, k1b.y * qb.y);
            *(uint4*)(outb + (size_t)ch * 8192
                       + (size_t)(((s * 8 + mtile) * 32 + lane) * 16)) = o;
        }
    }
}

// ---------------------------------------------------------------------------
// Kernel 3: q/k projections via fp16 mma, 2-pass. grid (8, 8, 2) x 256.
// mat==0 writes q fp32 ; mat==1 writes k fp16.
// ---------------------------------------------------------------------------
#define QK_STAGE 24576
#define QK_SMEM  (3 * QK_STAGE)

__global__ __launch_bounds__(256) void qk_mma_kernel()
{
    extern __shared__ char sm[];
    const int tid = threadIdx.x;
    const int ot  = blockIdx.x;
    const int mt  = blockIdx.y;
    const int mat = blockIdx.z;
    const int w    = tid >> 5, lane = tid & 31;
    const int mh   = w & 1;
    const int nq   = w >> 1;

    const uint8_t* atiles = g_Xt + (size_t)mt * (NCHUNK * 8192);
    const uint8_t* wtiles = g_Wqk + (size_t)((mat * 8 + ot) * NCHUNK) * 16384;

    float acc[4][4][4];
    #pragma unroll
    for (int a = 0; a < 4; a++)
        #pragma unroll
        for (int c = 0; c < 4; c++)
            #pragma unroll
            for (int e = 0; e < 4; e++) acc[a][c][e] = 0.f;

    auto produce = [&](int ch) {
        char* stg = sm + (ch % 3) * QK_STAGE;
        const uint32_t d = smem_u32(stg) + tid * 16;
        const uint8_t* sA = atiles + (size_t)ch * 8192 + tid * 16;
        CP_ASYNC16(d,        sA);
        CP_ASYNC16(d + 4096, sA + 4096);
        const uint8_t* sW = wtiles + (size_t)ch * 16384 + tid * 16;
        #pragma unroll
        for (int i = 0; i < 4; i++)
            CP_ASYNC16(d + 8192 + i * 4096, sW + i * 4096);
        CP_COMMIT();
    };

    auto consume = [&](int ch) {
        const char* stg = sm + (ch % 3) * QK_STAGE;
        const char* Ah = stg;
        const char* Wh = stg + 8192;
        const char* Wl = stg + 16384;
        #pragma unroll
        for (int s = 0; s < 2; s++) {
            uint32_t a[4][4];
            #pragma unroll
            for (int mtc = 0; mtc < 4; mtc++) {
                uint4 v4 = *(const uint4*)(Ah + ((size_t)((s * 8 + mh * 4 + mtc) * 32 + lane)) * 16);
                a[mtc][0] = v4.x; a[mtc][1] = v4.y; a[mtc][2] = v4.z; a[mtc][3] = v4.w;
            }
            uint32_t bh[4][2], bl[4][2];
            #pragma unroll
            for (int p = 0; p < 2; p++) {
                uint4 uh = *(const uint4*)(Wh + ((size_t)((s * 8 + nq * 2 + p) * 32 + lane)) * 16);
                uint4 ul = *(const uint4*)(Wl + ((size_t)((s * 8 + nq * 2 + p) * 32 + lane)) * 16);
                bh[p*2+0][0] = uh.x; bh[p*2+0][1] = uh.y;
                bh[p*2+1][0] = uh.z; bh[p*2+1][1] = uh.w;
                bl[p*2+0][0] = ul.x; bl[p*2+0][1] = ul.y;
                bl[p*2+1][0] = ul.z; bl[p*2+1][1] = ul.w;
            }
            #pragma unroll
            for (int mtc = 0; mtc < 4; mtc++)
                #pragma unroll
                for (int nf = 0; nf < 4; nf++) {
                    MMA_F16(acc[mtc][nf], a[mtc], bh[nf]);
                    MMA_F16(acc[mtc][nf], a[mtc], bl[nf]);
                }
        }
    };

    produce(0); produce(1);
    for (int ch = 0; ch < NCHUNK; ch++) {
        if (ch == NCHUNK - 1) { CP_WAIT0(); } else { CP_WAIT1(); }
        __syncthreads();
        if (ch + 2 < NCHUNK) produce(ch + 2);
        consume(ch);
    }

    const int colbase = ot * 128 + nq * 32 + (lane & 3) * 2;
    if (mat == 0) {
        #pragma unroll
        for (int mtc = 0; mtc < 4; mtc++) {
            const int row = mt * 128 + mh * 64 + mtc * 16 + (lane >> 2);
            #pragma unroll
            for (int nf = 0; nf < 4; nf++) {
                const int col = colbase + nf * 8;
                *(float2*)(g_q + (size_t)row * Hsz + col) =
                    make_float2(acc[mtc][nf][0], acc[mtc][nf][1]);
                *(float2*)(g_q + (size_t)(row + 8) * Hsz + col) =
                    make_float2(acc[mtc][nf][2], acc[mtc][nf][3]);
            }
        }
    } else {
        #pragma unroll
        for (int mtc = 0; mtc < 4; mtc++) {
            const int row = mt * 128 + mh * 64 + mtc * 16 + (lane >> 2);
            #pragma unroll
            for (int nf = 0; nf < 4; nf++) {
                const int col = colbase + nf * 8;
                *(uint32_t*)(g_kh + (size_t)row * Hsz + col) =
                    pack_f16(acc[mtc][nf][0], acc[mtc][nf][1]);
                *(uint32_t*)(g_kh + (size_t)(row + 8) * Hsz + col) =
                    pack_f16(acc[mtc][nf][2], acc[mtc][nf][3]);
            }
        }
    }
}

// ---------------------------------------------------------------------------
// Kernel 4: PERSISTENT logits contraction, 1-pass fp16, N=256 per tile,
// 64-k chunks, 4-stage x 48KB cp.async ring (depth-3 prefetch, wait_group 2).
// grid 148 x 256, 1 CTA/SM; tiles = bi*4 + nt2; ring runs across tiles.
// stage 48KB: [A 16K][W0 16K][W1 16K].
// ---------------------------------------------------------------------------
#define LG_STAGE 49152
#define LG_SMEM  (4 * LG_STAGE)

__global__ __launch_bounds__(256, 1) void logits_mma_kernel(float* __restrict__ out)
{
    extern __shared__ char sm[];
    const int tid = threadIdx.x;
    const int w    = tid >> 5, lane = tid & 31;
    const int mh   = w & 1;              // j half
    const int nq   = w >> 1;             // 0..3 -> 64 cols
    const int woff = (nq >> 1) * 16384;
    const int nfp0 = (nq & 1) * 4;

    // number of tiles for this CTA and total chunk count
    const int ntiles = (NTILE - (int)blockIdx.x + NPERS - 1) / NPERS;
    const int GTOT   = ntiles * LG_NCH;

    // produce global chunk g: tile index = bid + (g/16)*148, chunk = g%16
    auto produce = [&](int g) {
        const int t   = (int)blockIdx.x + (g >> 4) * NPERS;
        const int ch  = g & (LG_NCH - 1);
        const int nt2 = t & 3;
        const int bi  = t >> 2;
        char* stg = sm + (g & 3) * LG_STAGE;
        const uint32_t d = smem_u32(stg) + tid * 16;
        const uint8_t* sA  = g_At + (size_t)bi * (NCHUNK * 8192) + (size_t)ch * 16384 + tid * 16;
        const uint8_t* sw0 = g_Wt + (size_t)((nt2 * 2 + 0) * NCHUNK) * 8192 + (size_t)ch * 16384 + tid * 16;
        const uint8_t* sw1 = g_Wt + (size_t)((nt2 * 2 + 1) * NCHUNK) * 8192 + (size_t)ch * 16384 + tid * 16;
        #pragma unroll
        for (int i = 0; i < 4; i++) CP_ASYNC16(d + i * 4096,         sA  + i * 4096);
        #pragma unroll
        for (int i = 0; i < 4; i++) CP_ASYNC16(d + 16384 + i * 4096, sw0 + i * 4096);
        #pragma unroll
        for (int i = 0; i < 4; i++) CP_ASYNC16(d + 32768 + i * 4096, sw1 + i * 4096);
        CP_COMMIT();
    };

    float acc[4][8][4];
    int gp = 0, gc = 0;
    #pragma unroll
    for (int i = 0; i < 3; i++) { if (gp < GTOT) { produce(gp); gp++; } }

    for (int ti = 0; ti < ntiles; ti++) {
        const int t = (int)blockIdx.x + ti * NPERS;
        #pragma unroll
        for (int a = 0; a < 4; a++)
            #pragma unroll
            for (int c = 0; c < 8; c++)
                #pragma unroll
                for (int e = 0; e < 4; e++) acc[a][c][e] = 0.f;

        for (int ch = 0; ch < LG_NCH; ch++) {
            const int newer = gp - 1 - gc;
            if (newer >= 2)      { CP_WAIT2(); }
            else if (newer == 1) { CP_WAIT1(); }
            else                 { CP_WAIT0(); }
            __syncthreads();
            if (gp < GTOT) { produce(gp); gp++; }
            // consume stage (gc & 3)
            {
                const char* stg = sm + (gc & 3) * LG_STAGE;
                #pragma unroll
                for (int cc = 0; cc < 2; cc++) {
                    const char* Ah = stg + cc * 8192;
                    const char* Wt = stg + 16384 + woff + cc * 8192;
                    #pragma unroll
                    for (int s = 0; s < 2; s++) {
                        uint32_t a[4][4];
                        #pragma unroll
                        for (int mtc = 0; mtc < 4; mtc++) {
                            uint4 v4 = *(const uint4*)(Ah + ((size_t)((s * 8 + mh * 4 + mtc) * 32 + lane)) * 16);
                            a[mtc][0] = v4.x; a[mtc][1] = v4.y; a[mtc][2] = v4.z; a[mtc][3] = v4.w;
                        }
                        uint32_t bfr[8][2];
                        #pragma unroll
                        for (int p = 0; p < 4; p++) {
                            uint4 u = *(const uint4*)(Wt + ((size_t)((s * 8 + nfp0 + p) * 32 + lane)) * 16);
                            bfr[p*2+0][0] = u.x; bfr[p*2+0][1] = u.y;
                            bfr[p*2+1][0] = u.z; bfr[p*2+1][1] = u.w;
                        }
                        #pragma unroll
                        for (int mtc = 0; mtc < 4; mtc++)
                            #pragma unroll
                            for (int nf = 0; nf < 8; nf++)
                                MMA_F16(acc[mtc][nf], a[mtc], bfr[nf]);
                    }
                }
            }
            gc++;
        }

        // epilogue for tile t (overlaps in-flight copies of next tile)
        const int nt2 = t & 3;
        const int bi  = t >> 2;
        const size_t rowbase = (size_t)bi * 128;
        const int colbase = nt2 * 256 + (nq >> 1) * 128 + (nq & 1) * 64 + (lane & 3) * 2;
        #pragma unroll
        for (int mtc = 0; mtc < 4; mtc++) {
            const int j0e = mh * 64 + mtc * 16 + (lane >> 2);
            #pragma unroll
            for (int nf = 0; nf < 8; nf++) {
                const int col = colbase + nf * 8;
                float* p0 = out + OFF_LOGITS + (rowbase + j0e) * (size_t)VV + col;
                float* p1 = out + OFF_LOGITS + (rowbase + j0e + 8) * (size_t)VV + col;
                *(float2*)p0 = make_float2(acc[mtc][nf][0], acc[mtc][nf][1]);
                *(float2*)p1 = make_float2(acc[mtc][nf][2], acc[mtc][nf][3]);
            }
        }
    }
}

// ---------------------------------------------------------------------------
// Kernel F: merged mask outputs, 1024-thread blocks.
// blocks [0,2048): pair ; [2048,2176): diag ; [2176,2184): mask_aa.
// ---------------------------------------------------------------------------
__global__ __launch_bounds__(1024) void finalize_kernel(
    const int* __restrict__ mask_idx, float* __restrict__ out)
{
    __shared__ uint32_t bm[32];
    const int bz = blockIdx.x, t = threadIdx.x;

    if (bz < 2048) {
        const int b   = bz >> 8;
        const int grp = bz & 255;
        if (t < 32) bm[t] = 0;
        __syncthreads();
        if (t < Msz) {
            int mi = mask_idx[b * Msz + t];
            atomicOr(&bm[mi >> 5], 1u << (mi & 31));
        }
        __syncthreads();
        const int l1 = grp * 4 + (t >> 8);
        const int c  = t & 255;
        const float s1 = (float)((bm[l1 >> 5] >> (l1 & 31)) & 1u);
        const int l2 = c * 4;
        float4 o;
        o.x = s1 * (float)((bm[(l2 + 0) >> 5] >> ((l2 + 0) & 31)) & 1u);
        o.y = s1 * (float)((bm[(l2 + 1) >> 5] >> ((l2 + 1) & 31)) & 1u);
        o.z = s1 * (float)((bm[(l2 + 2) >> 5] >> ((l2 + 2) & 31)) & 1u);
        o.w = s1 * (float)((bm[(l2 + 3) >> 5] >> ((l2 + 3) & 31)) & 1u);
        ((float4*)(out + OFF_PAIR))[((size_t)(b * Lsz + l1)) * 256 + c] = o;
    } else if (bz < 2176) {
        const int idx = (bz - 2048) * 1024 + t;
        const int r = idx & (Msz * Msz - 1);
        const int i = r >> 7, j = r & 127;
        out[OFF_DIAG + idx] = (i == j) ? 1.0f : 0.0f;
    } else {
        const int b = bz - 2176;
        if (t < 32) bm[t] = 0;
        __syncthreads();
        if (t < Msz) {
            int mi = mask_idx[b * Msz + t];
            atomicOr(&bm[mi >> 5], 1u << (mi & 31));
        }
        __syncthreads();
        out[OFF_MASKAA + (size_t)b * Lsz + t] = (float)((bm[t >> 5] >> (t & 31)) & 1u);
    }
}

// ---------------------------------------------------------------------------
// Launch
// ---------------------------------------------------------------------------
extern "C" void kernel_launch(void* const* d_in, const int* in_sizes, int n_in,
                              void* d_out, int out_size)
{
    const float* x_enc    = (const float*)d_in[0];
    const float* ln_gamma = (const float*)d_in[1];
    const float* ln_beta  = (const float*)d_in[2];
    const float* Wq       = (const float*)d_in[3];
    const float* Wk       = (const float*)d_in[4];
    const float* W_embed  = (const float*)d_in[5];
    const float* W_mlm    = (const float*)d_in[6];
    const int*   mask_idx = (const int*)d_in[7];
    float* out = (float*)d_out;

    cudaFuncSetAttribute(qk_mma_kernel,
                         cudaFuncAttributeMaxDynamicSharedMemorySize, QK_SMEM);
    cudaFuncSetAttribute(logits_mma_kernel,
                         cudaFuncAttributeMaxDynamicSharedMemorySize, LG_SMEM);

    prep_kernel<<<904, 256>>>(W_embed, Wq, Wk, W_mlm, mask_idx);
    ln_mlm_kernel<<<Bsz * Lsz / 8, 256>>>(x_enc, ln_gamma, ln_beta, out);
    xmsplit_kernel<<<8, 256>>>();
    qk_mma_kernel<<<dim3(8, 8, 2), 256, QK_SMEM>>>();
    asplit_kernel<<<1024, 256>>>();
    logits_mma_kernel<<<NPERS, 256, LG_SMEM>>>(out);
    finalize_kernel<<<2184, 1024>>>(mask_idx, out);
}

// round 16
// speedup vs baseline: 1.0504x; 1.0504x over previous
#include <cuda_runtime.h>
#include <cuda_fp16.h>
#include <cstdint>
#include <cstddef>

// ---------------------------------------------------------------------------
// Problem constants
// ---------------------------------------------------------------------------
#define Bsz 8
#define Lsz 1024
#define Hsz 1024
#define Msz 128
#define Vsz 32
#define VV  (Vsz * Vsz)          // 1024
#define LN_EPS 1e-5f
#define NCHUNK 32                // storage granularity: K chunks of 32
#define NCH3   8                 // logits: K chunks of 128
#define NTILE  4096              // logits work items (4 ntile-pairs x 1024 bi)
#define NPERS  148               // persistent CTAs

// Output layout offsets (floats)
static const size_t OFF_LOGITS = 0;
static const size_t OFF_MLM    = 134217728;
static const size_t OFF_DIAG   = OFF_MLM + (size_t)Bsz * Lsz * Vsz;
static const size_t OFF_MASKAA = OFF_DIAG + (size_t)Bsz * Msz * Msz;
static const size_t OFF_PAIR   = OFF_MASKAA + (size_t)Bsz * Lsz;

// ---------------------------------------------------------------------------
// Device scratch
// ---------------------------------------------------------------------------
__device__ float  g_xm[(size_t)Bsz * Msz * Hsz];     // 4 MB (gathered LN rows)
__device__ float  g_q [(size_t)Bsz * Msz * Hsz];     // 4 MB
__device__ __half g_kh[(size_t)Bsz * Msz * Hsz];     // 2 MB (k in fp16)
__device__ int    g_inv[Bsz * Lsz];                  // l -> m (or -1)
__device__ float  g_Wmt[Hsz * Vsz];                  // W_mlm transposed [h][v]

// W_embed fp16 (single-rounded), mma B-frag paired-nf layout per (nt, chunk32)
__device__ __align__(1024) uint8_t g_Wt[8 * NCHUNK * 8192];            // 2 MB
// Wq/Wk split hi/lo fp16: [mat(2)][ot(8)][chunk(32)] x 16KB = [hi|lo]
__device__ __align__(1024) uint8_t g_Wqk[2 * 8 * NCHUNK * 16384];      // 8 MB
// xm fp16 A-frag: [mtile(8)][chunk(32)] x 8KB
__device__ __align__(1024) uint8_t g_Xt[8 * NCHUNK * 8192];            // 2 MB
// A' = q (.) k fp16 A-frag per (bi, chunk32)
__device__ __align__(1024) uint8_t g_At[(size_t)1024 * NCHUNK * 8192]; // 256 MB

// ---------------------------------------------------------------------------
// Helpers
// ---------------------------------------------------------------------------
__device__ __forceinline__ uint32_t smem_u32(const void* p) {
    uint32_t a;
    asm("{ .reg .u64 t; cvta.to.shared.u64 t, %1; cvt.u32.u64 %0, t; }"
        : "=r"(a) : "l"(p));
    return a;
}

__device__ __forceinline__ uint32_t pack_f16(float lo, float hi) {
    uint32_t r;
    asm("cvt.rn.f16x2.f32 %0, %1, %2;" : "=r"(r) : "f"(hi), "f"(lo));
    return r;
}
__device__ __forceinline__ void split2_f16(float x0, float x1, uint32_t& h, uint32_t& l) {
    h = pack_f16(x0, x1);
    float h0, h1;
    asm("{.reg .f16 a,b; mov.b32 {a,b}, %2; cvt.f32.f16 %0, a; cvt.f32.f16 %1, b;}"
        : "=f"(h0), "=f"(h1) : "r"(h));
    l = pack_f16(x0 - h0, x1 - h1);
}

#define CP_ASYNC16(dst_u32, src_ptr) \
    asm volatile("cp.async.cg.shared.global [%0], [%1], 16;" \
                 :: "r"(dst_u32), "l"(src_ptr) : "memory")
#define CP_COMMIT()  asm volatile("cp.async.commit_group;" ::: "memory")
#define CP_WAIT0()   asm volatile("cp.async.wait_group 0;" ::: "memory")
#define CP_WAIT1()   asm volatile("cp.async.wait_group 1;" ::: "memory")

#define MMA_F16(c, a, bb) \
    asm volatile("mma.sync.aligned.m16n8k16.row.col.f32.f16.f16.f32 " \
                 "{%0,%1,%2,%3},{%4,%5,%6,%7},{%8,%9},{%0,%1,%2,%3};" \
                 : "+f"((c)[0]), "+f"((c)[1]), "+f"((c)[2]), "+f"((c)[3]) \
                 : "r"((a)[0]), "r"((a)[1]), "r"((a)[2]), "r"((a)[3]), \
                   "r"((bb)[0]), "r"((bb)[1]))

// ---------------------------------------------------------------------------
// Kernel Pw: weight splits (W_embed + Wq/Wk). grid 768 x 256. (side stream)
// ---------------------------------------------------------------------------
__global__ __launch_bounds__(256) void prep_w_kernel(
    const float* __restrict__ W, const float* __restrict__ Wq,
    const float* __restrict__ Wk)
{
    const int bz = blockIdx.x, tid = threadIdx.x;

    if (bz < 256) {
        const int ch = bz & 31, nt = bz >> 5;
        const int v  = tid >> 1;
        const int sh = tid & 1;
        const float4* src = (const float4*)(W + (size_t)(nt * 128 + v) * Hsz + ch * 32 + sh * 16);
        uint8_t* tile = g_Wt + (size_t)(nt * NCHUNK + ch) * 8192;
        const int nfp  = v >> 4;
        const int half = (v >> 3) & 1;
        const int lbase = (v & 7) * 4;
        #pragma unroll
        for (int g = 0; g < 4; g++) {
            float4 x = src[g];
            #pragma unroll
            for (int e = 0; e < 2; e++) {
                const int pl = g * 2 + e;
                uint32_t h = (e == 0) ? pack_f16(x.x, x.y) : pack_f16(x.z, x.w);
                const uint32_t off =
                    (uint32_t)(((sh * 8 + nfp) * 32 + lbase + (pl & 3)) * 16 + half * 8 + (pl >> 2) * 4);
                *(uint32_t*)(tile + off) = h;
            }
        }
    } else {
        const int idx = bz - 256;
        const int ch = idx & 31, ot = (idx >> 5) & 7, mat = idx >> 8;
        const float* Wx = mat ? Wk : Wq;
        const int v  = tid >> 1;
        const int sh = tid & 1;
        const float4* src = (const float4*)(Wx + (size_t)(ot * 128 + v) * Hsz + ch * 32 + sh * 16);
        uint8_t* tile = g_Wqk + (size_t)((mat * 8 + ot) * NCHUNK + ch) * 16384;
        const int nfp  = v >> 4;
        const int half = (v >> 3) & 1;
        const int lbase = (v & 7) * 4;
        #pragma unroll
        for (int g = 0; g < 4; g++) {
            float4 x = src[g];
            #pragma unroll
            for (int e = 0; e < 2; e++) {
                const int pl = g * 2 + e;
                uint32_t h, l;
                if (e == 0) split2_f16(x.x, x.y, h, l);
                else        split2_f16(x.z, x.w, h, l);
                const uint32_t off =
                    (uint32_t)(((sh * 8 + nfp) * 32 + lbase + (pl & 3)) * 16 + half * 8 + (pl >> 2) * 4);
                *(uint32_t*)(tile + off)        = h;
                *(uint32_t*)(tile + 8192 + off) = l;
            }
        }
    }
}

// ---------------------------------------------------------------------------
// Kernel Ps: W_mlm transpose + inverse mask index. grid 136 x 256. (main)
// blocks [0,128): wmlmT ; [128,136): inv
// ---------------------------------------------------------------------------
__global__ __launch_bounds__(256) void prep_s_kernel(
    const float* __restrict__ Wm, const int* __restrict__ mask_idx)
{
    const int bz = blockIdx.x, tid = threadIdx.x;
    if (bz < 128) {
        const int idx = bz * 256 + tid;
        const int h = idx >> 5, v = idx & 31;
        g_Wmt[idx] = Wm[(size_t)v * Hsz + h];
    } else {
        const int b = bz - 128;
        #pragma unroll
        for (int i = tid; i < Lsz; i += 256) g_inv[b * Lsz + i] = -1;
        __syncthreads();
        if (tid < Msz) g_inv[b * Lsz + mask_idx[b * Msz + tid]] = tid;
    }
}

// ---------------------------------------------------------------------------
// Kernel 1: LayerNorm (warp-per-row) + MLM (transposed W) + fused gather.
// ---------------------------------------------------------------------------
__global__ __launch_bounds__(256) void ln_mlm_kernel(
    const float* __restrict__ x, const float* __restrict__ gamma,
    const float* __restrict__ beta, float* __restrict__ out)
{
    __shared__ float sx[8][Hsz];          // 32 KB
    __shared__ float red[8][8][Vsz];      // 8 KB
    const int w = threadIdx.x >> 5, l = threadIdx.x & 31;
    const int row = blockIdx.x * 8 + w;
    const int b   = row >> 10;

    const float4* xr = (const float4*)(x + (size_t)row * Hsz);
    const float4* g4p = (const float4*)gamma;
    const float4* b4p = (const float4*)beta;
    float4 v[8];
    float s = 0.f, ss = 0.f;
    #pragma unroll
    for (int i = 0; i < 8; i++) {
        v[i] = xr[l + i * 32];
        s  += v[i].x + v[i].y + v[i].z + v[i].w;
        ss += v[i].x*v[i].x + v[i].y*v[i].y + v[i].z*v[i].z + v[i].w*v[i].w;
    }
    #pragma unroll
    for (int o = 16; o; o >>= 1) {
        s  += __shfl_xor_sync(0xffffffffu, s,  o);
        ss += __shfl_xor_sync(0xffffffffu, ss, o);
    }
    const float mu = s * (1.0f / Hsz);
    const float rs = rsqrtf(ss * (1.0f / Hsz) - mu * mu + LN_EPS);

    const int inv = g_inv[row];
    float4* xm4 = (float4*)(g_xm + (size_t)(b * Msz + (inv < 0 ? 0 : inv)) * Hsz);
    float4* sx4 = (float4*)sx[w];
    #pragma unroll
    for (int i = 0; i < 8; i++) {
        float4 g = g4p[l + i * 32];
        float4 bb = b4p[l + i * 32];
        float4 n;
        n.x = (v[i].x - mu) * rs * g.x + bb.x;
        n.y = (v[i].y - mu) * rs * g.y + bb.y;
        n.z = (v[i].z - mu) * rs * g.z + bb.z;
        n.w = (v[i].w - mu) * rs * g.w + bb.w;
        sx4[l + i * 32] = n;
        if (inv >= 0) xm4[l + i * 32] = n;
    }
    __syncthreads();

    float p[8];
    #pragma unroll
    for (int r = 0; r < 8; r++) p[r] = 0.f;
    const float* wt = g_Wmt + (size_t)(w * 128) * Vsz + l;
    #pragma unroll 4
    for (int hh = 0; hh < 128; hh++) {
        const int h = w * 128 + hh;
        float wv = wt[hh * Vsz];
        #pragma unroll
        for (int r = 0; r < 8; r++) p[r] += sx[r][h] * wv;
    }
    #pragma unroll
    for (int r = 0; r < 8; r++) red[w][r][l] = p[r];
    __syncthreads();

    float acc = 0.f;
    #pragma unroll
    for (int ww = 0; ww < 8; ww++) acc += red[ww][w][l];
    out[OFF_MLM + (size_t)row * Vsz + l] = acc;
}

// ---------------------------------------------------------------------------
// Kernel 0c: xm -> fp16 A-frag tiles. grid (8 mtiles) x 256.
// ---------------------------------------------------------------------------
__global__ __launch_bounds__(256) void xmsplit_kernel()
{
    const int mt = blockIdx.x;
    const int tid = threadIdx.x;
    const int mt16 = tid >> 5;
    const int lane = tid & 31;
    const int j0 = mt * 128 + mt16 * 16 + (lane >> 2);
    const int j1 = j0 + 8;
    const int kq = (lane & 3) * 2;
    const float* x0 = g_xm + (size_t)j0 * Hsz;
    const float* x1 = g_xm + (size_t)j1 * Hsz;
    uint8_t* outb = g_Xt + (size_t)mt * (NCHUNK * 8192);

    for (int ch = 0; ch < NCHUNK; ch++) {
        #pragma unroll
        for (int s = 0; s < 2; s++) {
            const int kk = ch * 32 + s * 16 + kq;
            float2 a0 = *(const float2*)(x0 + kk);
            float2 a1 = *(const float2*)(x1 + kk);
            float2 b0 = *(const float2*)(x0 + kk + 8);
            float2 b1 = *(const float2*)(x1 + kk + 8);
            uint4 o;
            o.x = pack_f16(a0.x, a0.y);
            o.y = pack_f16(a1.x, a1.y);
            o.z = pack_f16(b0.x, b0.y);
            o.w = pack_f16(b1.x, b1.y);
            *(uint4*)(outb + (size_t)ch * 8192
                       + (size_t)(((s * 8 + mt16) * 32 + lane) * 16)) = o;
        }
    }
}

// ---------------------------------------------------------------------------
// Kernel A: A' = q (.) k fp16 A-frag per bi (k read as fp16). grid 1024 x 256.
// ---------------------------------------------------------------------------
__global__ __launch_bounds__(256) void asplit_kernel()
{
    const int bi = blockIdx.x;
    const int b  = bi >> 7;
    const int tid = threadIdx.x;
    const int mtile = tid >> 5;
    const int lane  = tid & 31;
    const int j0 = mtile * 16 + (lane >> 2);
    const int j1 = j0 + 8;
    const int kq = (lane & 3) * 2;

    const float*  qrow = g_q + (size_t)bi * Hsz;
    const __half* k0r  = g_kh + (size_t)(b * Msz + j0) * Hsz;
    const __half* k1r  = g_kh + (size_t)(b * Msz + j1) * Hsz;
    uint8_t* outb = g_At + (size_t)bi * (NCHUNK * 8192);

    for (int ch = 0; ch < NCHUNK; ch++) {
        #pragma unroll
        for (int s = 0; s < 2; s++) {
            const int kk = ch * 32 + s * 16 + kq;
            float2 qa  = *(const float2*)(qrow + kk);
            float2 qb  = *(const float2*)(qrow + kk + 8);
            float2 k0a = __half22float2(*(const __half2*)(k0r + kk));
            float2 k0b = __half22float2(*(const __half2*)(k0r + kk + 8));
            float2 k1a = __half22float2(*(const __half2*)(k1r + kk));
            float2 k1b = __half22float2(*(const __half2*)(k1r + kk + 8));
            uint4 o;
            o.x = pack_f16(k0a.x * qa.x, k0a.y * qa.y);
            o.y = pack_f16(k1a.x * qa.x, k1a.y * qa.y);
            o.z = pack_f16(k0b.x * qb.x, k0b.y * qb.y);
            o.w = pack_f16(k1b.x * qb.x, k1b.y * qb.y);
            *(uint4*)(outb + (size_t)ch * 8192
                       + (size_t)(((s * 8 + mtile) * 32 + lane) * 16)) = o;
        }
    }
}

// ---------------------------------------------------------------------------
// Kernel 3: q/k projections via fp16 mma, 2-pass. grid (8, 8, 2) x 256.
// mat==0 writes q fp32 ; mat==1 writes k fp16.
// ---------------------------------------------------------------------------
#define QK_STAGE 24576
#define QK_SMEM  (3 * QK_STAGE)

__global__ __launch_bounds__(256) void qk_mma_kernel()
{
    extern __shared__ char sm[];
    const int tid = threadIdx.x;
    const int ot  = blockIdx.x;
    const int mt  = blockIdx.y;
    const int mat = blockIdx.z;
    const int w    = tid >> 5, lane = tid & 31;
    const int mh   = w & 1;
    const int nq   = w >> 1;

    const uint8_t* atiles = g_Xt + (size_t)mt * (NCHUNK * 8192);
    const uint8_t* wtiles = g_Wqk + (size_t)((mat * 8 + ot) * NCHUNK) * 16384;

    float acc[4][4][4];
    #pragma unroll
    for (int a = 0; a < 4; a++)
        #pragma unroll
        for (int c = 0; c < 4; c++)
            #pragma unroll
            for (int e = 0; e < 4; e++) acc[a][c][e] = 0.f;

    auto produce = [&](int ch) {
        char* stg = sm + (ch % 3) * QK_STAGE;
        const uint32_t d = smem_u32(stg) + tid * 16;
        const uint8_t* sA = atiles + (size_t)ch * 8192 + tid * 16;
        CP_ASYNC16(d,        sA);
        CP_ASYNC16(d + 4096, sA + 4096);
        const uint8_t* sW = wtiles + (size_t)ch * 16384 + tid * 16;
        #pragma unroll
        for (int i = 0; i < 4; i++)
            CP_ASYNC16(d + 8192 + i * 4096, sW + i * 4096);
        CP_COMMIT();
    };

    auto consume = [&](int ch) {
        const char* stg = sm + (ch % 3) * QK_STAGE;
        const char* Ah = stg;
        const char* Wh = stg + 8192;
        const char* Wl = stg + 16384;
        #pragma unroll
        for (int s = 0; s < 2; s++) {
            uint32_t a[4][4];
            #pragma unroll
            for (int mtc = 0; mtc < 4; mtc++) {
                uint4 v4 = *(const uint4*)(Ah + ((size_t)((s * 8 + mh * 4 + mtc) * 32 + lane)) * 16);
                a[mtc][0] = v4.x; a[mtc][1] = v4.y; a[mtc][2] = v4.z; a[mtc][3] = v4.w;
            }
            uint32_t bh[4][2], bl[4][2];
            #pragma unroll
            for (int p = 0; p < 2; p++) {
                uint4 uh = *(const uint4*)(Wh + ((size_t)((s * 8 + nq * 2 + p) * 32 + lane)) * 16);
                uint4 ul = *(const uint4*)(Wl + ((size_t)((s * 8 + nq * 2 + p) * 32 + lane)) * 16);
                bh[p*2+0][0] = uh.x; bh[p*2+0][1] = uh.y;
                bh[p*2+1][0] = uh.z; bh[p*2+1][1] = uh.w;
                bl[p*2+0][0] = ul.x; bl[p*2+0][1] = ul.y;
                bl[p*2+1][0] = ul.z; bl[p*2+1][1] = ul.w;
            }
            #pragma unroll
            for (int mtc = 0; mtc < 4; mtc++)
                #pragma unroll
                for (int nf = 0; nf < 4; nf++) {
                    MMA_F16(acc[mtc][nf], a[mtc], bh[nf]);
                    MMA_F16(acc[mtc][nf], a[mtc], bl[nf]);
                }
        }
    };

    produce(0); produce(1);
    for (int ch = 0; ch < NCHUNK; ch++) {
        if (ch == NCHUNK - 1) { CP_WAIT0(); } else { CP_WAIT1(); }
        __syncthreads();
        if (ch + 2 < NCHUNK) produce(ch + 2);
        consume(ch);
    }

    const int colbase = ot * 128 + nq * 32 + (lane & 3) * 2;
    if (mat == 0) {
        #pragma unroll
        for (int mtc = 0; mtc < 4; mtc++) {
            const int row = mt * 128 + mh * 64 + mtc * 16 + (lane >> 2);
            #pragma unroll
            for (int nf = 0; nf < 4; nf++) {
                const int col = colbase + nf * 8;
                *(float2*)(g_q + (size_t)row * Hsz + col) =
                    make_float2(acc[mtc][nf][0], acc[mtc][nf][1]);
                *(float2*)(g_q + (size_t)(row + 8) * Hsz + col) =
                    make_float2(acc[mtc][nf][2], acc[mtc][nf][3]);
            }
        }
    } else {
        #pragma unroll
        for (int mtc = 0; mtc < 4; mtc++) {
            const int row = mt * 128 + mh * 64 + mtc * 16 + (lane >> 2);
            #pragma unroll
            for (int nf = 0; nf < 4; nf++) {
                const int col = colbase + nf * 8;
                *(uint32_t*)(g_kh + (size_t)row * Hsz + col) =
                    pack_f16(acc[mtc][nf][0], acc[mtc][nf][1]);
                *(uint32_t*)(g_kh + (size_t)(row + 8) * Hsz + col) =
                    pack_f16(acc[mtc][nf][2], acc[mtc][nf][3]);
            }
        }
    }
}

// ---------------------------------------------------------------------------
// Kernel 4: PERSISTENT logits contraction (R14-proven), 1-pass fp16,
// N=256 per tile, 128-k chunks. grid 148 x 256, 1 CTA/SM.
// stage 96KB: [A 32K][W0 32K][W1 32K] x 2 stages (192KB).
// ---------------------------------------------------------------------------
#define LG_STAGE 98304
#define LG_SMEM  (2 * LG_STAGE)

__global__ __launch_bounds__(256, 1) void logits_mma_kernel(float* __restrict__ out)
{
    extern __shared__ char sm[];
    const int tid = threadIdx.x;
    const int w    = tid >> 5, lane = tid & 31;
    const int mh   = w & 1;              // j half
    const int nq   = w >> 1;             // 0..3 -> 64 cols
    const int woff = (nq >> 1) * 32768;
    const int nfp0 = (nq & 1) * 4;

    auto produce = [&](int tile, int ch, int st) {
        const int nt2 = tile & 3;
        const int bi  = tile >> 2;
        char* stg = sm + st * LG_STAGE;
        const uint32_t d = smem_u32(stg) + tid * 16;
        const uint8_t* sA  = g_At + (size_t)bi * (NCHUNK * 8192) + (size_t)ch * 32768 + tid * 16;
        const uint8_t* sw0 = g_Wt + (size_t)((nt2 * 2 + 0) * NCHUNK) * 8192 + (size_t)ch * 32768 + tid * 16;
        const uint8_t* sw1 = g_Wt + (size_t)((nt2 * 2 + 1) * NCHUNK) * 8192 + (size_t)ch * 32768 + tid * 16;
        #pragma unroll
        for (int i = 0; i < 8; i++) CP_ASYNC16(d + i * 4096,         sA  + i * 4096);
        #pragma unroll
        for (int i = 0; i < 8; i++) CP_ASYNC16(d + 32768 + i * 4096, sw0 + i * 4096);
        #pragma unroll
        for (int i = 0; i < 8; i++) CP_ASYNC16(d + 65536 + i * 4096, sw1 + i * 4096);
        CP_COMMIT();
    };

    float acc[4][8][4];

    int st = 0;
    produce(blockIdx.x, 0, 0);

    for (int t = blockIdx.x; t < NTILE; t += NPERS) {
        #pragma unroll
        for (int a = 0; a < 4; a++)
            #pragma unroll
            for (int c = 0; c < 8; c++)
                #pragma unroll
                for (int e = 0; e < 4; e++) acc[a][c][e] = 0.f;

        for (int ch = 0; ch < NCH3; ch++) {
            CP_WAIT0();
            __syncthreads();
            {
                int ntile = t, nch = ch + 1;
                if (nch == NCH3) { ntile = t + NPERS; nch = 0; }
                if (ntile < NTILE) produce(ntile, nch, st ^ 1);
            }
            {
                const char* stg = sm + st * LG_STAGE;
                #pragma unroll
                for (int cc = 0; cc < 4; cc++) {
                    const char* Ah = stg + cc * 8192;
                    const char* Wt = stg + 32768 + woff + cc * 8192;
                    #pragma unroll
                    for (int s = 0; s < 2; s++) {
                        uint32_t a[4][4];
                        #pragma unroll
                        for (int mtc = 0; mtc < 4; mtc++) {
                            uint4 v4 = *(const uint4*)(Ah + ((size_t)((s * 8 + mh * 4 + mtc) * 32 + lane)) * 16);
                            a[mtc][0] = v4.x; a[mtc][1] = v4.y; a[mtc][2] = v4.z; a[mtc][3] = v4.w;
                        }
                        uint32_t bfr[8][2];
                        #pragma unroll
                        for (int p = 0; p < 4; p++) {
                            uint4 u = *(const uint4*)(Wt + ((size_t)((s * 8 + nfp0 + p) * 32 + lane)) * 16);
                            bfr[p*2+0][0] = u.x; bfr[p*2+0][1] = u.y;
                            bfr[p*2+1][0] = u.z; bfr[p*2+1][1] = u.w;
                        }
                        #pragma unroll
                        for (int mtc = 0; mtc < 4; mtc++)
                            #pragma unroll
                            for (int nf = 0; nf < 8; nf++)
                                MMA_F16(acc[mtc][nf], a[mtc], bfr[nf]);
                    }
                }
            }
            st ^= 1;
        }

        const int nt2 = t & 3;
        const int bi  = t >> 2;
        const size_t rowbase = (size_t)bi * 128;
        const int colbase = nt2 * 256 + (nq >> 1) * 128 + (nq & 1) * 64 + (lane & 3) * 2;
        #pragma unroll
        for (int mtc = 0; mtc < 4; mtc++) {
            const int j0e = mh * 64 + mtc * 16 + (lane >> 2);
            #pragma unroll
            for (int nf = 0; nf < 8; nf++) {
                const int col = colbase + nf * 8;
                float* p0 = out + OFF_LOGITS + (rowbase + j0e) * (size_t)VV + col;
                float* p1 = out + OFF_LOGITS + (rowbase + j0e + 8) * (size_t)VV + col;
                *(float2*)p0 = make_float2(acc[mtc][nf][0], acc[mtc][nf][1]);
                *(float2*)p1 = make_float2(acc[mtc][nf][2], acc[mtc][nf][3]);
            }
        }
    }
}

// ---------------------------------------------------------------------------
// Kernel F: merged mask outputs, 1024-thread blocks. (side stream)
// blocks [0,2048): pair ; [2048,2176): diag ; [2176,2184): mask_aa.
// ---------------------------------------------------------------------------
__global__ __launch_bounds__(1024) void finalize_kernel(
    const int* __restrict__ mask_idx, float* __restrict__ out)
{
    __shared__ uint32_t bm[32];
    const int bz = blockIdx.x, t = threadIdx.x;

    if (bz < 2048) {
        const int b   = bz >> 8;
        const int grp = bz & 255;
        if (t < 32) bm[t] = 0;
        __syncthreads();
        if (t < Msz) {
            int mi = mask_idx[b * Msz + t];
            atomicOr(&bm[mi >> 5], 1u << (mi & 31));
        }
        __syncthreads();
        const int l1 = grp * 4 + (t >> 8);
        const int c  = t & 255;
        const float s1 = (float)((bm[l1 >> 5] >> (l1 & 31)) & 1u);
        const int l2 = c * 4;
        float4 o;
        o.x = s1 * (float)((bm[(l2 + 0) >> 5] >> ((l2 + 0) & 31)) & 1u);
        o.y = s1 * (float)((bm[(l2 + 1) >> 5] >> ((l2 + 1) & 31)) & 1u);
        o.z = s1 * (float)((bm[(l2 + 2) >> 5] >> ((l2 + 2) & 31)) & 1u);
        o.w = s1 * (float)((bm[(l2 + 3) >> 5] >> ((l2 + 3) & 31)) & 1u);
        ((float4*)(out + OFF_PAIR))[((size_t)(b * Lsz + l1)) * 256 + c] = o;
    } else if (bz < 2176) {
        const int idx = (bz - 2048) * 1024 + t;
        const int r = idx & (Msz * Msz - 1);
        const int i = r >> 7, j = r & 127;
        out[OFF_DIAG + idx] = (i == j) ? 1.0f : 0.0f;
    } else {
        const int b = bz - 2176;
        if (t < 32) bm[t] = 0;
        __syncthreads();
        if (t < Msz) {
            int mi = mask_idx[b * Msz + t];
            atomicOr(&bm[mi >> 5], 1u << (mi & 31));
        }
        __syncthreads();
        out[OFF_MASKAA + (size_t)b * Lsz + t] = (float)((bm[t >> 5] >> (t & 31)) & 1u);
    }
}

// ---------------------------------------------------------------------------
// Launch (stream-forked DAG; all capture-legal, no allocations)
// ---------------------------------------------------------------------------
extern "C" void kernel_launch(void* const* d_in, const int* in_sizes, int n_in,
                              void* d_out, int out_size)
{
    const float* x_enc    = (const float*)d_in[0];
    const float* ln_gamma = (const float*)d_in[1];
    const float* ln_beta  = (const float*)d_in[2];
    const float* Wq       = (const float*)d_in[3];
    const float* Wk       = (const float*)d_in[4];
    const float* W_embed  = (const float*)d_in[5];
    const float* W_mlm    = (const float*)d_in[6];
    const int*   mask_idx = (const int*)d_in[7];
    float* out = (float*)d_out;

    static cudaStream_t sB = nullptr, sC = nullptr;
    static cudaEvent_t evRoot = nullptr, evRoot2 = nullptr, evB = nullptr, evC = nullptr;
    if (sB == nullptr) {
        cudaStreamCreateWithFlags(&sB, cudaStreamNonBlocking);
        cudaStreamCreateWithFlags(&sC, cudaStreamNonBlocking);
        cudaEventCreateWithFlags(&evRoot,  cudaEventDisableTiming);
        cudaEventCreateWithFlags(&evRoot2, cudaEventDisableTiming);
        cudaEventCreateWithFlags(&evB, cudaEventDisableTiming);
        cudaEventCreateWithFlags(&evC, cudaEventDisableTiming);
        cudaFuncSetAttribute(qk_mma_kernel,
                             cudaFuncAttributeMaxDynamicSharedMemorySize, QK_SMEM);
        cudaFuncSetAttribute(logits_mma_kernel,
                             cudaFuncAttributeMaxDynamicSharedMemorySize, LG_SMEM);
    }

    // fork side streams from the origin stream
    cudaEventRecord(evRoot, 0);
    cudaStreamWaitEvent(sB, evRoot, 0);
    cudaEventRecord(evRoot2, 0);
    cudaStreamWaitEvent(sC, evRoot2, 0);

    // stream C: independent mask outputs (overlaps entire main chain)
    finalize_kernel<<<2184, 1024, 0, sC>>>(mask_idx, out);
    cudaEventRecord(evC, sC);

    // stream B: weight splits (needed only by qk_mma / logits)
    prep_w_kernel<<<768, 256, 0, sB>>>(W_embed, Wq, Wk);
    cudaEventRecord(evB, sB);

    // main chain
    prep_s_kernel<<<136, 256>>>(W_mlm, mask_idx);
    ln_mlm_kernel<<<Bsz * Lsz / 8, 256>>>(x_enc, ln_gamma, ln_beta, out);
    xmsplit_kernel<<<8, 256>>>();
    cudaStreamWaitEvent(0, evB, 0);     // join weight splits before qk
    qk_mma_kernel<<<dim3(8, 8, 2), 256, QK_SMEM>>>();
    asplit_kernel<<<1024, 256>>>();
    logits_mma_kernel<<<NPERS, 256, LG_SMEM>>>(out);
    cudaStreamWaitEvent(0, evC, 0);     // join finalize
}

// round 17
// speedup vs baseline: 1.1221x; 1.0682x over previous
#include <cuda_runtime.h>
#include <cuda_fp16.h>
#include <cstdint>
#include <cstddef>

// ---------------------------------------------------------------------------
// Problem constants
// ---------------------------------------------------------------------------
#define Bsz 8
#define Lsz 1024
#define Hsz 1024
#define Msz 128
#define Vsz 32
#define VV  (Vsz * Vsz)          // 1024
#define LN_EPS 1e-5f
#define NCHUNK 32                // storage granularity: K chunks of 32
#define NCH3   8                 // logits: K chunks of 128
#define NTILE  4096              // logits work items (4 ntile-pairs x 1024 bi)
#define NPERS  148               // persistent CTAs

// Output layout offsets (floats)
static const size_t OFF_LOGITS = 0;
static const size_t OFF_MLM    = 134217728;
static const size_t OFF_DIAG   = OFF_MLM + (size_t)Bsz * Lsz * Vsz;
static const size_t OFF_MASKAA = OFF_DIAG + (size_t)Bsz * Msz * Msz;
static const size_t OFF_PAIR   = OFF_MASKAA + (size_t)Bsz * Lsz;

// ---------------------------------------------------------------------------
// Device scratch
// ---------------------------------------------------------------------------
__device__ float  g_xm[(size_t)Bsz * Msz * Hsz];     // 4 MB (gathered LN rows)
__device__ __half g_qh[(size_t)Bsz * Msz * Hsz];     // 2 MB (q fp16 rows)
__device__ int    g_inv[Bsz * Lsz];                  // l -> m (or -1)
__device__ float  g_Wmt[Hsz * Vsz];                  // W_mlm transposed [h][v]

// k in mma A-frag layout per (b, chunk32): [b(8)][ch32(32)] x 8KB
__device__ __align__(1024) uint8_t g_Kt[8 * NCHUNK * 8192];            // 2 MB
// W_embed fp16 (single-rounded), mma B-frag paired-nf layout per (nt, chunk32)
__device__ __align__(1024) uint8_t g_Wt[8 * NCHUNK * 8192];            // 2 MB
// Wq/Wk split hi/lo fp16: [mat(2)][ot(8)][chunk(32)] x 16KB = [hi|lo]
__device__ __align__(1024) uint8_t g_Wqk[2 * 8 * NCHUNK * 16384];      // 8 MB
// xm fp16 A-frag: [mtile(8)][chunk(32)] x 8KB
__device__ __align__(1024) uint8_t g_Xt[8 * NCHUNK * 8192];            // 2 MB

// ---------------------------------------------------------------------------
// Helpers
// ---------------------------------------------------------------------------
__device__ __forceinline__ uint32_t smem_u32(const void* p) {
    uint32_t a;
    asm("{ .reg .u64 t; cvta.to.shared.u64 t, %1; cvt.u32.u64 %0, t; }"
        : "=r"(a) : "l"(p));
    return a;
}

__device__ __forceinline__ uint32_t pack_f16(float lo, float hi) {
    uint32_t r;
    asm("cvt.rn.f16x2.f32 %0, %1, %2;" : "=r"(r) : "f"(hi), "f"(lo));
    return r;
}
__device__ __forceinline__ void split2_f16(float x0, float x1, uint32_t& h, uint32_t& l) {
    h = pack_f16(x0, x1);
    float h0, h1;
    asm("{.reg .f16 a,b; mov.b32 {a,b}, %2; cvt.f32.f16 %0, a; cvt.f32.f16 %1, b;}"
        : "=f"(h0), "=f"(h1) : "r"(h));
    l = pack_f16(x0 - h0, x1 - h1);
}

#define CP_ASYNC16(dst_u32, src_ptr) \
    asm volatile("cp.async.cg.shared.global [%0], [%1], 16;" \
                 :: "r"(dst_u32), "l"(src_ptr) : "memory")
#define CP_COMMIT()  asm volatile("cp.async.commit_group;" ::: "memory")
#define CP_WAIT0()   asm volatile("cp.async.wait_group 0;" ::: "memory")
#define CP_WAIT1()   asm volatile("cp.async.wait_group 1;" ::: "memory")

#define MMA_F16(c, a, bb) \
    asm volatile("mma.sync.aligned.m16n8k16.row.col.f32.f16.f16.f32 " \
                 "{%0,%1,%2,%3},{%4,%5,%6,%7},{%8,%9},{%0,%1,%2,%3};" \
                 : "+f"((c)[0]), "+f"((c)[1]), "+f"((c)[2]), "+f"((c)[3]) \
                 : "r"((a)[0]), "r"((a)[1]), "r"((a)[2]), "r"((a)[3]), \
                   "r"((bb)[0]), "r"((bb)[1]))

#define HMUL2(d, a, b) \
    asm("mul.rn.f16x2 %0, %1, %2;" : "=r"(d) : "r"(a), "r"(b))

// ---------------------------------------------------------------------------
// Kernel Pw: weight splits (W_embed + Wq/Wk). grid 768 x 256. (side stream)
// ---------------------------------------------------------------------------
__global__ __launch_bounds__(256) void prep_w_kernel(
    const float* __restrict__ W, const float* __restrict__ Wq,
    const float* __restrict__ Wk)
{
    const int bz = blockIdx.x, tid = threadIdx.x;

    if (bz < 256) {
        const int ch = bz & 31, nt = bz >> 5;
        const int v  = tid >> 1;
        const int sh = tid & 1;
        const float4* src = (const float4*)(W + (size_t)(nt * 128 + v) * Hsz + ch * 32 + sh * 16);
        uint8_t* tile = g_Wt + (size_t)(nt * NCHUNK + ch) * 8192;
        const int nfp  = v >> 4;
        const int half = (v >> 3) & 1;
        const int lbase = (v & 7) * 4;
        #pragma unroll
        for (int g = 0; g < 4; g++) {
            float4 x = src[g];
            #pragma unroll
            for (int e = 0; e < 2; e++) {
                const int pl = g * 2 + e;
                uint32_t h = (e == 0) ? pack_f16(x.x, x.y) : pack_f16(x.z, x.w);
                const uint32_t off =
                    (uint32_t)(((sh * 8 + nfp) * 32 + lbase + (pl & 3)) * 16 + half * 8 + (pl >> 2) * 4);
                *(uint32_t*)(tile + off) = h;
            }
        }
    } else {
        const int idx = bz - 256;
        const int ch = idx & 31, ot = (idx >> 5) & 7, mat = idx >> 8;
        const float* Wx = mat ? Wk : Wq;
        const int v  = tid >> 1;
        const int sh = tid & 1;
        const float4* src = (const float4*)(Wx + (size_t)(ot * 128 + v) * Hsz + ch * 32 + sh * 16);
        uint8_t* tile = g_Wqk + (size_t)((mat * 8 + ot) * NCHUNK + ch) * 16384;
        const int nfp  = v >> 4;
        const int half = (v >> 3) & 1;
        const int lbase = (v & 7) * 4;
        #pragma unroll
        for (int g = 0; g < 4; g++) {
            float4 x = src[g];
            #pragma unroll
            for (int e = 0; e < 2; e++) {
                const int pl = g * 2 + e;
                uint32_t h, l;
                if (e == 0) split2_f16(x.x, x.y, h, l);
                else        split2_f16(x.z, x.w, h, l);
                const uint32_t off =
                    (uint32_t)(((sh * 8 + nfp) * 32 + lbase + (pl & 3)) * 16 + half * 8 + (pl >> 2) * 4);
                *(uint32_t*)(tile + off)        = h;
                *(uint32_t*)(tile + 8192 + off) = l;
            }
        }
    }
}

// ---------------------------------------------------------------------------
// Kernel Ps: W_mlm transpose + inverse mask index. grid 136 x 256. (main)
// ---------------------------------------------------------------------------
__global__ __launch_bounds__(256) void prep_s_kernel(
    const float* __restrict__ Wm, const int* __restrict__ mask_idx)
{
    const int bz = blockIdx.x, tid = threadIdx.x;
    if (bz < 128) {
        const int idx = bz * 256 + tid;
        const int h = idx >> 5, v = idx & 31;
        g_Wmt[idx] = Wm[(size_t)v * Hsz + h];
    } else {
        const int b = bz - 128;
        #pragma unroll
        for (int i = tid; i < Lsz; i += 256) g_inv[b * Lsz + i] = -1;
        __syncthreads();
        if (tid < Msz) g_inv[b * Lsz + mask_idx[b * Msz + tid]] = tid;
    }
}

// ---------------------------------------------------------------------------
// Kernel 1: LayerNorm (warp-per-row) + MLM (transposed W) + fused gather.
// ---------------------------------------------------------------------------
__global__ __launch_bounds__(256) void ln_mlm_kernel(
    const float* __restrict__ x, const float* __restrict__ gamma,
    const float* __restrict__ beta, float* __restrict__ out)
{
    __shared__ float sx[8][Hsz];          // 32 KB
    __shared__ float red[8][8][Vsz];      // 8 KB
    const int w = threadIdx.x >> 5, l = threadIdx.x & 31;
    const int row = blockIdx.x * 8 + w;
    const int b   = row >> 10;

    const float4* xr = (const float4*)(x + (size_t)row * Hsz);
    const float4* g4p = (const float4*)gamma;
    const float4* b4p = (const float4*)beta;
    float4 v[8];
    float s = 0.f, ss = 0.f;
    #pragma unroll
    for (int i = 0; i < 8; i++) {
        v[i] = xr[l + i * 32];
        s  += v[i].x + v[i].y + v[i].z + v[i].w;
        ss += v[i].x*v[i].x + v[i].y*v[i].y + v[i].z*v[i].z + v[i].w*v[i].w;
    }
    #pragma unroll
    for (int o = 16; o; o >>= 1) {
        s  += __shfl_xor_sync(0xffffffffu, s,  o);
        ss += __shfl_xor_sync(0xffffffffu, ss, o);
    }
    const float mu = s * (1.0f / Hsz);
    const float rs = rsqrtf(ss * (1.0f / Hsz) - mu * mu + LN_EPS);

    const int inv = g_inv[row];
    float4* xm4 = (float4*)(g_xm + (size_t)(b * Msz + (inv < 0 ? 0 : inv)) * Hsz);
    float4* sx4 = (float4*)sx[w];
    #pragma unroll
    for (int i = 0; i < 8; i++) {
        float4 g = g4p[l + i * 32];
        float4 bb = b4p[l + i * 32];
        float4 n;
        n.x = (v[i].x - mu) * rs * g.x + bb.x;
        n.y = (v[i].y - mu) * rs * g.y + bb.y;
        n.z = (v[i].z - mu) * rs * g.z + bb.z;
        n.w = (v[i].w - mu) * rs * g.w + bb.w;
        sx4[l + i * 32] = n;
        if (inv >= 0) xm4[l + i * 32] = n;
    }
    __syncthreads();

    float p[8];
    #pragma unroll
    for (int r = 0; r < 8; r++) p[r] = 0.f;
    const float* wt = g_Wmt + (size_t)(w * 128) * Vsz + l;
    #pragma unroll 4
    for (int hh = 0; hh < 128; hh++) {
        const int h = w * 128 + hh;
        float wv = wt[hh * Vsz];
        #pragma unroll
        for (int r = 0; r < 8; r++) p[r] += sx[r][h] * wv;
    }
    #pragma unroll
    for (int r = 0; r < 8; r++) red[w][r][l] = p[r];
    __syncthreads();

    float acc = 0.f;
    #pragma unroll
    for (int ww = 0; ww < 8; ww++) acc += red[ww][w][l];
    out[OFF_MLM + (size_t)row * Vsz + l] = acc;
}

// ---------------------------------------------------------------------------
// Kernel 0c: xm -> fp16 A-frag tiles. grid (8 mtiles) x 256.
// ---------------------------------------------------------------------------
__global__ __launch_bounds__(256) void xmsplit_kernel()
{
    const int mt = blockIdx.x;
    const int tid = threadIdx.x;
    const int mt16 = tid >> 5;
    const int lane = tid & 31;
    const int j0 = mt * 128 + mt16 * 16 + (lane >> 2);
    const int j1 = j0 + 8;
    const int kq = (lane & 3) * 2;
    const float* x0 = g_xm + (size_t)j0 * Hsz;
    const float* x1 = g_xm + (size_t)j1 * Hsz;
    uint8_t* outb = g_Xt + (size_t)mt * (NCHUNK * 8192);

    for (int ch = 0; ch < NCHUNK; ch++) {
        #pragma unroll
        for (int s = 0; s < 2; s++) {
            const int kk = ch * 32 + s * 16 + kq;
            float2 a0 = *(const float2*)(x0 + kk);
            float2 a1 = *(const float2*)(x1 + kk);
            float2 b0 = *(const float2*)(x0 + kk + 8);
            float2 b1 = *(const float2*)(x1 + kk + 8);
            uint4 o;
            o.x = pack_f16(a0.x, a0.y);
            o.y = pack_f16(a1.x, a1.y);
            o.z = pack_f16(b0.x, b0.y);
            o.w = pack_f16(b1.x, b1.y);
            *(uint4*)(outb + (size_t)ch * 8192
                       + (size_t)(((s * 8 + mt16) * 32 + lane) * 16)) = o;
        }
    }
}

// ---------------------------------------------------------------------------
// Kernel 3: q/k projections via fp16 mma, 2-pass. grid (8, 8, 2) x 256.
// mat==0 writes q fp16 rows (g_qh) ; mat==1 writes k in A-frag layout (g_Kt).
// ---------------------------------------------------------------------------
#define QK_STAGE 24576
#define QK_SMEM  (3 * QK_STAGE)

__global__ __launch_bounds__(256) void qk_mma_kernel()
{
    extern __shared__ char sm[];
    const int tid = threadIdx.x;
    const int ot  = blockIdx.x;
    const int mt  = blockIdx.y;
    const int mat = blockIdx.z;
    const int w    = tid >> 5, lane = tid & 31;
    const int mh   = w & 1;
    const int nq   = w >> 1;

    const uint8_t* atiles = g_Xt + (size_t)mt * (NCHUNK * 8192);
    const uint8_t* wtiles = g_Wqk + (size_t)((mat * 8 + ot) * NCHUNK) * 16384;

    float acc[4][4][4];
    #pragma unroll
    for (int a = 0; a < 4; a++)
        #pragma unroll
        for (int c = 0; c < 4; c++)
            #pragma unroll
            for (int e = 0; e < 4; e++) acc[a][c][e] = 0.f;

    auto produce = [&](int ch) {
        char* stg = sm + (ch % 3) * QK_STAGE;
        const uint32_t d = smem_u32(stg) + tid * 16;
        const uint8_t* sA = atiles + (size_t)ch * 8192 + tid * 16;
        CP_ASYNC16(d,        sA);
        CP_ASYNC16(d + 4096, sA + 4096);
        const uint8_t* sW = wtiles + (size_t)ch * 16384 + tid * 16;
        #pragma unroll
        for (int i = 0; i < 4; i++)
            CP_ASYNC16(d + 8192 + i * 4096, sW + i * 4096);
        CP_COMMIT();
    };

    auto consume = [&](int ch) {
        const char* stg = sm + (ch % 3) * QK_STAGE;
        const char* Ah = stg;
        const char* Wh = stg + 8192;
        const char* Wl = stg + 16384;
        #pragma unroll
        for (int s = 0; s < 2; s++) {
            uint32_t a[4][4];
            #pragma unroll
            for (int mtc = 0; mtc < 4; mtc++) {
                uint4 v4 = *(const uint4*)(Ah + ((size_t)((s * 8 + mh * 4 + mtc) * 32 + lane)) * 16);
                a[mtc][0] = v4.x; a[mtc][1] = v4.y; a[mtc][2] = v4.z; a[mtc][3] = v4.w;
            }
            uint32_t bh[4][2], bl[4][2];
            #pragma unroll
            for (int p = 0; p < 2; p++) {
                uint4 uh = *(const uint4*)(Wh + ((size_t)((s * 8 + nq * 2 + p) * 32 + lane)) * 16);
                uint4 ul = *(const uint4*)(Wl + ((size_t)((s * 8 + nq * 2 + p) * 32 + lane)) * 16);
                bh[p*2+0][0] = uh.x; bh[p*2+0][1] = uh.y;
                bh[p*2+1][0] = uh.z; bh[p*2+1][1] = uh.w;
                bl[p*2+0][0] = ul.x; bl[p*2+0][1] = ul.y;
                bl[p*2+1][0] = ul.z; bl[p*2+1][1] = ul.w;
            }
            #pragma unroll
            for (int mtc = 0; mtc < 4; mtc++)
                #pragma unroll
                for (int nf = 0; nf < 4; nf++) {
                    MMA_F16(acc[mtc][nf], a[mtc], bh[nf]);
                    MMA_F16(acc[mtc][nf], a[mtc], bl[nf]);
                }
        }
    };

    produce(0); produce(1);
    for (int ch = 0; ch < NCHUNK; ch++) {
        if (ch == NCHUNK - 1) { CP_WAIT0(); } else { CP_WAIT1(); }
        __syncthreads();
        if (ch + 2 < NCHUNK) produce(ch + 2);
        consume(ch);
    }

    if (mat == 0) {
        // q: fp16 row layout
        const int colbase = ot * 128 + nq * 32 + (lane & 3) * 2;
        #pragma unroll
        for (int mtc = 0; mtc < 4; mtc++) {
            const int row = mt * 128 + mh * 64 + mtc * 16 + (lane >> 2);
            #pragma unroll
            for (int nf = 0; nf < 4; nf++) {
                const int col = colbase + nf * 8;
                *(uint32_t*)(g_qh + (size_t)row * Hsz + col) =
                    pack_f16(acc[mtc][nf][0], acc[mtc][nf][1]);
                *(uint32_t*)(g_qh + (size_t)(row + 8) * Hsz + col) =
                    pack_f16(acc[mtc][nf][2], acc[mtc][nf][3]);
            }
        }
    } else {
        // k: write directly into mma A-frag layout (b = mt)
        uint8_t* ktb = g_Kt + (size_t)mt * (NCHUNK * 8192);
        const int ch32 = ot * 4 + nq;
        #pragma unroll
        for (int mtc = 0; mtc < 4; mtc++) {
            const int mtile16 = mh * 4 + mtc;
            #pragma unroll
            for (int nf = 0; nf < 4; nf++) {
                const int s = (nf >> 1) & 1;
                const uint32_t off = (uint32_t)(ch32 * 8192
                    + ((s * 8 + mtile16) * 32 + lane) * 16 + (nf & 1) * 8);
                uint2 o;
                o.x = pack_f16(acc[mtc][nf][0], acc[mtc][nf][1]);   // areg pair lo (j0)
                o.y = pack_f16(acc[mtc][nf][2], acc[mtc][nf][3]);   // areg pair hi (j0+8)
                *(uint2*)(ktb + off) = o;
            }
        }
    }
}

// ---------------------------------------------------------------------------
// Kernel 4: PERSISTENT logits contraction, 1-pass fp16, N=256 per tile,
// 128-k chunks. A-frags built on the fly: Kt frag * q broadcast (HMUL2).
// grid 148 x 256, 1 CTA/SM. stage: [Kt 32K][W0 32K][W1 32K][q 256B] x 2.
// ---------------------------------------------------------------------------
#define LG_STAGE 98560
#define LG_SMEM  (2 * LG_STAGE)
#define LG_QOFF  98304

__global__ __launch_bounds__(256, 1) void logits_mma_kernel(float* __restrict__ out)
{
    extern __shared__ char sm[];
    const int tid = threadIdx.x;
    const int w    = tid >> 5, lane = tid & 31;
    const int mh   = w & 1;              // j half
    const int nq   = w >> 1;             // 0..3 -> 64 cols
    const int woff = (nq >> 1) * 32768;
    const int nfp0 = (nq & 1) * 4;
    const int qoff = (lane & 3) * 4;

    auto produce = [&](int tile, int ch, int st) {
        const int nt2 = tile & 3;
        const int bi  = tile >> 2;
        const int b   = bi >> 7;
        char* stg = sm + st * LG_STAGE;
        const uint32_t d = smem_u32(stg) + tid * 16;
        const uint8_t* sK  = g_Kt + ((size_t)(b * NCHUNK + ch * 4)) * 8192 + tid * 16;
        const uint8_t* sw0 = g_Wt + (size_t)((nt2 * 2 + 0) * NCHUNK) * 8192 + (size_t)ch * 32768 + tid * 16;
        const uint8_t* sw1 = g_Wt + (size_t)((nt2 * 2 + 1) * NCHUNK) * 8192 + (size_t)ch * 32768 + tid * 16;
        #pragma unroll
        for (int i = 0; i < 8; i++) CP_ASYNC16(d + i * 4096,         sK  + i * 4096);
        #pragma unroll
        for (int i = 0; i < 8; i++) CP_ASYNC16(d + 32768 + i * 4096, sw0 + i * 4096);
        #pragma unroll
        for (int i = 0; i < 8; i++) CP_ASYNC16(d + 65536 + i * 4096, sw1 + i * 4096);
        if (tid < 16) {
            const uint8_t* sq = (const uint8_t*)(g_qh + (size_t)bi * Hsz + ch * 128) + tid * 16;
            CP_ASYNC16(smem_u32(stg + LG_QOFF) + tid * 16, sq);
        }
        CP_COMMIT();
    };

    float acc[4][8][4];

    int st = 0;
    produce(blockIdx.x, 0, 0);

    for (int t = blockIdx.x; t < NTILE; t += NPERS) {
        #pragma unroll
        for (int a = 0; a < 4; a++)
            #pragma unroll
            for (int c = 0; c < 8; c++)
                #pragma unroll
                for (int e = 0; e < 4; e++) acc[a][c][e] = 0.f;

        for (int ch = 0; ch < NCH3; ch++) {
            CP_WAIT0();
            __syncthreads();
            {
                int ntile = t, nch = ch + 1;
                if (nch == NCH3) { ntile = t + NPERS; nch = 0; }
                if (ntile < NTILE) produce(ntile, nch, st ^ 1);
            }
            {
                const char* stg = sm + st * LG_STAGE;
                #pragma unroll
                for (int cc = 0; cc < 4; cc++) {
                    const char* Ah = stg + cc * 8192;
                    const char* Wt = stg + 32768 + woff + cc * 8192;
                    const char* qc = stg + LG_QOFF + cc * 64;
                    #pragma unroll
                    for (int s = 0; s < 2; s++) {
                        const uint32_t qa = *(const uint32_t*)(qc + s * 32 + qoff);
                        const uint32_t qb = *(const uint32_t*)(qc + s * 32 + 16 + qoff);
                        uint32_t a[4][4];
                        #pragma unroll
                        for (int mtc = 0; mtc < 4; mtc++) {
                            uint4 v4 = *(const uint4*)(Ah + ((size_t)((s * 8 + mh * 4 + mtc) * 32 + lane)) * 16);
                            HMUL2(a[mtc][0], v4.x, qa);
                            HMUL2(a[mtc][1], v4.y, qa);
                            HMUL2(a[mtc][2], v4.z, qb);
                            HMUL2(a[mtc][3], v4.w, qb);
                        }
                        uint32_t bfr[8][2];
                        #pragma unroll
                        for (int p = 0; p < 4; p++) {
                            uint4 u = *(const uint4*)(Wt + ((size_t)((s * 8 + nfp0 + p) * 32 + lane)) * 16);
                            bfr[p*2+0][0] = u.x; bfr[p*2+0][1] = u.y;
                            bfr[p*2+1][0] = u.z; bfr[p*2+1][1] = u.w;
                        }
                        #pragma unroll
                        for (int mtc = 0; mtc < 4; mtc++)
                            #pragma unroll
                            for (int nf = 0; nf < 8; nf++)
                                MMA_F16(acc[mtc][nf], a[mtc], bfr[nf]);
                    }
                }
            }
            st ^= 1;
        }

        const int nt2 = t & 3;
        const int bi  = t >> 2;
        const size_t rowbase = (size_t)bi * 128;
        const int colbase = nt2 * 256 + (nq >> 1) * 128 + (nq & 1) * 64 + (lane & 3) * 2;
        #pragma unroll
        for (int mtc = 0; mtc < 4; mtc++) {
            const int j0e = mh * 64 + mtc * 16 + (lane >> 2);
            #pragma unroll
            for (int nf = 0; nf < 8; nf++) {
                const int col = colbase + nf * 8;
                float* p0 = out + OFF_LOGITS + (rowbase + j0e) * (size_t)VV + col;
                float* p1 = out + OFF_LOGITS + (rowbase + j0e + 8) * (size_t)VV + col;
                *(float2*)p0 = make_float2(acc[mtc][nf][0], acc[mtc][nf][1]);
                *(float2*)p1 = make_float2(acc[mtc][nf][2], acc[mtc][nf][3]);
            }
        }
    }
}

// ---------------------------------------------------------------------------
// Kernel F: merged mask outputs, 1024-thread blocks. (side stream)
// ---------------------------------------------------------------------------
__global__ __launch_bounds__(1024) void finalize_kernel(
    const int* __restrict__ mask_idx, float* __restrict__ out)
{
    __shared__ uint32_t bm[32];
    const int bz = blockIdx.x, t = threadIdx.x;

    if (bz < 2048) {
        const int b   = bz >> 8;
        const int grp = bz & 255;
        if (t < 32) bm[t] = 0;
        __syncthreads();
        if (t < Msz) {
            int mi = mask_idx[b * Msz + t];
            atomicOr(&bm[mi >> 5], 1u << (mi & 31));
        }
        __syncthreads();
        const int l1 = grp * 4 + (t >> 8);
        const int c  = t & 255;
        const float s1 = (float)((bm[l1 >> 5] >> (l1 & 31)) & 1u);
        const int l2 = c * 4;
        float4 o;
        o.x = s1 * (float)((bm[(l2 + 0) >> 5] >> ((l2 + 0) & 31)) & 1u);
        o.y = s1 * (float)((bm[(l2 + 1) >> 5] >> ((l2 + 1) & 31)) & 1u);
        o.z = s1 * (float)((bm[(l2 + 2) >> 5] >> ((l2 + 2) & 31)) & 1u);
        o.w = s1 * (float)((bm[(l2 + 3) >> 5] >> ((l2 + 3) & 31)) & 1u);
        ((float4*)(out + OFF_PAIR))[((size_t)(b * Lsz + l1)) * 256 + c] = o;
    } else if (bz < 2176) {
        const int idx = (bz - 2048) * 1024 + t;
        const int r = idx & (Msz * Msz - 1);
        const int i = r >> 7, j = r & 127;
        out[OFF_DIAG + idx] = (i == j) ? 1.0f : 0.0f;
    } else {
        const int b = bz - 2176;
        if (t < 32) bm[t] = 0;
        __syncthreads();
        if (t < Msz) {
            int mi = mask_idx[b * Msz + t];
            atomicOr(&bm[mi >> 5], 1u << (mi & 31));
        }
        __syncthreads();
        out[OFF_MASKAA + (size_t)b * Lsz + t] = (float)((bm[t >> 5] >> (t & 31)) & 1u);
    }
}

// ---------------------------------------------------------------------------
// Launch (stream-forked DAG; all capture-legal, no allocations)
// ---------------------------------------------------------------------------
extern "C" void kernel_launch(void* const* d_in, const int* in_sizes, int n_in,
                              void* d_out, int out_size)
{
    const float* x_enc    = (const float*)d_in[0];
    const float* ln_gamma = (const float*)d_in[1];
    const float* ln_beta  = (const float*)d_in[2];
    const float* Wq       = (const float*)d_in[3];
    const float* Wk       = (const float*)d_in[4];
    const float* W_embed  = (const float*)d_in[5];
    const float* W_mlm    = (const float*)d_in[6];
    const int*   mask_idx = (const int*)d_in[7];
    float* out = (float*)d_out;

    static cudaStream_t sB = nullptr, sC = nullptr;
    static cudaEvent_t evRoot = nullptr, evRoot2 = nullptr, evB = nullptr, evC = nullptr;
    if (sB == nullptr) {
        cudaStreamCreateWithFlags(&sB, cudaStreamNonBlocking);
        cudaStreamCreateWithFlags(&sC, cudaStreamNonBlocking);
        cudaEventCreateWithFlags(&evRoot,  cudaEventDisableTiming);
        cudaEventCreateWithFlags(&evRoot2, cudaEventDisableTiming);
        cudaEventCreateWithFlags(&evB, cudaEventDisableTiming);
        cudaEventCreateWithFlags(&evC, cudaEventDisableTiming);
        cudaFuncSetAttribute(qk_mma_kernel,
                             cudaFuncAttributeMaxDynamicSharedMemorySize, QK_SMEM);
        cudaFuncSetAttribute(logits_mma_kernel,
                             cudaFuncAttributeMaxDynamicSharedMemorySize, LG_SMEM);
    }

    // fork side streams from the origin stream
    cudaEventRecord(evRoot, 0);
    cudaStreamWaitEvent(sB, evRoot, 0);
    cudaEventRecord(evRoot2, 0);
    cudaStreamWaitEvent(sC, evRoot2, 0);

    // stream C: independent mask outputs (overlaps entire main chain)
    finalize_kernel<<<2184, 1024, 0, sC>>>(mask_idx, out);
    cudaEventRecord(evC, sC);

    // stream B: weight splits (needed only by qk_mma / logits)
    prep_w_kernel<<<768, 256, 0, sB>>>(W_embed, Wq, Wk);
    cudaEventRecord(evB, sB);

    // main chain
    prep_s_kernel<<<136, 256>>>(W_mlm, mask_idx);
    ln_mlm_kernel<<<Bsz * Lsz / 8, 256>>>(x_enc, ln_gamma, ln_beta, out);
    xmsplit_kernel<<<8, 256>>>();
    cudaStreamWaitEvent(0, evB, 0);     // join weight splits before qk
    qk_mma_kernel<<<dim3(8, 8, 2), 256, QK_SMEM>>>();
    logits_mma_kernel<<<NPERS, 256, LG_SMEM>>>(out);
    cudaStreamWaitEvent(0, evC, 0);     // join finalize
}